// round 2
// baseline (speedup 1.0000x reference)
#include <cuda_runtime.h>

// Problem constants
#define AA 64        // number of sequences per set
#define MSEQ 128     // sequence length
#define DD 128       // feature dim
#define MMI 127      // number of increments (MSEQ-1)

#define NPAIR_TRI 2080                    // 64*65/2 upper-triangular pairs
#define NP (2*NPAIR_TRI + AA*AA)          // 2080 + 2080 + 4096 = 8256 blocks

// Shared memory layout (floats)
#define SA_STRIDE 132                     // 128 + 4 padding: conflict-free B-fragment LDS
#define OFF_B (128*SA_STRIDE)
#define OFF_M (2*128*SA_STRIDE)
#define SMEM_FLOATS (2*128*SA_STRIDE + 128*128)
#define SMEM_BYTES (SMEM_FLOATS*4)        // 200704 bytes

__device__ float g_partials[NP];

__global__ __launch_bounds__(256, 1)
void sig_block_kernel(const float* __restrict__ X, const float* __restrict__ Y) {
    extern __shared__ float smem[];
    float* sA = smem;            // 128 x 132 (dx, padded), reused as PDE diag buffers
    float* sB = smem + OFF_B;    // 128 x 132 (dy, padded)
    float* sM = smem + OFF_M;    // 128 x 128 (M matrix; row/col 127 garbage-free zeros)

    const int bid = blockIdx.x;
    const int tid = threadIdx.x;

    // ---- decode (gram type, pair) ----
    int g, a, b;
    float w;
    if (bid < 2 * NPAIR_TRI) {
        g = (bid < NPAIR_TRI) ? 0 : 1;
        int t = bid - g * NPAIR_TRI;
        int aa = 0;
        while (t >= (AA - aa)) { t -= (AA - aa); ++aa; }
        a = aa; b = aa + t;
        w = (a == b) ? 1.0f : 2.0f;       // symmetric gram: off-diag counted twice
    } else {
        g = 2;
        int t = bid - 2 * NPAIR_TRI;
        a = t >> 6; b = t & 63;
        w = -2.0f;                        // -2 * mean(K_XY)
    }
    const float* srcA = (g == 1) ? (Y + (size_t)a * MSEQ * DD) : (X + (size_t)a * MSEQ * DD);
    const float* srcB = (g == 0) ? (X + (size_t)b * MSEQ * DD) : (Y + (size_t)b * MSEQ * DD);

    // ---- load increments into smem (row 127 zero-padded) ----
    for (int idx = tid; idx < 128 * 128; idx += 256) {
        int i = idx >> 7, d = idx & 127;
        float va = 0.0f, vb = 0.0f;
        if (i < MMI) {
            va = srcA[(i + 1) * DD + d] - srcA[i * DD + d];
            vb = srcB[(i + 1) * DD + d] - srcB[i * DD + d];
        }
        sA[i * SA_STRIDE + d] = va;
        sB[i * SA_STRIDE + d] = vb;
    }
    __syncthreads();

    // ---- GEMM: sM[r][c] = sum_d sA[r][d] * sB[c][d]   (128x128x128, FP32) ----
    const int tx = tid & 15, ty = tid >> 4;
    const int r0 = ty * 8, c0 = tx * 8;

    float acc[64];
#pragma unroll
    for (int i = 0; i < 64; ++i) acc[i] = 0.0f;

#pragma unroll 2
    for (int d4 = 0; d4 < DD; d4 += 4) {
        float4 af[8], bf[8];
#pragma unroll
        for (int m = 0; m < 8; ++m)
            af[m] = *reinterpret_cast<const float4*>(&sA[(r0 + m) * SA_STRIDE + d4]);
#pragma unroll
        for (int n = 0; n < 8; ++n)
            bf[n] = *reinterpret_cast<const float4*>(&sB[(c0 + n) * SA_STRIDE + d4]);
#pragma unroll
        for (int m = 0; m < 8; ++m) {
#pragma unroll
            for (int n = 0; n < 8; ++n) {
                float s = acc[m * 8 + n];
                s = fmaf(af[m].x, bf[n].x, s);
                s = fmaf(af[m].y, bf[n].y, s);
                s = fmaf(af[m].z, bf[n].z, s);
                s = fmaf(af[m].w, bf[n].w, s);
                acc[m * 8 + n] = s;
            }
        }
    }

#pragma unroll
    for (int m = 0; m < 8; ++m)
#pragma unroll
        for (int n = 0; n < 8; ++n)
            sM[(r0 + m) * 128 + (c0 + n)] = acc[m * 8 + n];
    __syncthreads();   // sM visible; everyone is past sA/sB reads

    // ---- PDE: anti-diagonal wavefront over K (128x128, boundaries = 1) ----
    // K[p][q] = K[p][q-1] + K[p-1][q] + K[p-1][q-1]*(M[p-1][q-1]-1), p,q>=1
    // Rolling diagonal buffers live in the (now free) sA region.
    float* pp = sA;         // diag d-2
    float* pv = sA + 128;   // diag d-1
    float* cu = sA + 256;   // diag d

    float result = 0.0f;
    for (int d = 0; d <= 254; ++d) {
        if (tid < 128) {
            int q = d - tid;
            if (q >= 0 && q < 128) {
                float v;
                if (tid == 0 || q == 0) {
                    v = 1.0f;
                } else {
                    v = pv[tid] + pv[tid - 1]
                      + pp[tid - 1] * (sM[(tid - 1) * 128 + (q - 1)] - 1.0f);
                }
                cu[tid] = v;
                result = v;   // thread 127's final write (d=254) is K[127][127]
            }
        }
        __syncthreads();      // single barrier is sufficient: the buffer written
                              // at iter d+1 (old pp) was last read before this barrier
        float* t = pp; pp = pv; pv = cu; cu = t;
    }

    if (tid == 127) g_partials[bid] = w * result;
}

__global__ void sig_reduce_kernel(float* __restrict__ out) {
    __shared__ double sh[256];
    const int tid = threadIdx.x;
    double acc = 0.0;
    for (int i = tid; i < NP; i += 256) acc += (double)g_partials[i];
    sh[tid] = acc;
    __syncthreads();
    for (int s = 128; s > 0; s >>= 1) {
        if (tid < s) sh[tid] += sh[tid + s];
        __syncthreads();
    }
    if (tid == 0) out[0] = (float)(sh[0] * (1.0 / 4096.0));
}

extern "C" void kernel_launch(void* const* d_in, const int* in_sizes, int n_in,
                              void* d_out, int out_size) {
    const float* X = (const float*)d_in[0];
    const float* Y = (const float*)d_in[1];
    float* out = (float*)d_out;

    // Raise dynamic smem limit (host-side config, not a stream op — capture-safe)
    cudaFuncSetAttribute(sig_block_kernel,
                         cudaFuncAttributeMaxDynamicSharedMemorySize, SMEM_BYTES);

    sig_block_kernel<<<NP, 256, SMEM_BYTES>>>(X, Y);
    sig_reduce_kernel<<<1, 256>>>(out);
}

// round 3
// speedup vs baseline: 3.2095x; 3.2095x over previous
#include <cuda_runtime.h>

// Problem constants
#define AA 64        // sequences per set
#define MSEQ 128     // sequence length
#define DD 128       // feature dim
#define MMI 127      // increments (MSEQ-1)

#define NPAIR_TRI 2080                    // 64*65/2 upper-tri pairs
#define NP (2*NPAIR_TRI + AA*AA)          // 8256 blocks

// Shared memory layout (floats). Split-K: two 64-d chunks.
#define CH 64                              // d-chunk size
#define CS 68                              // chunk row stride (64+4): bank stride 4 => 2-way max
#define OFF_SB (128*CS)                    // 8704
#define SMEM_FLOATS (2*128*CS)             // 17408 floats = 69632 B (peak)
#define SMEM_BYTES (SMEM_FLOATS*4)
// Aliased PDE-phase layout: sM at 0 (16384 floats), diag buffers after it.
#define OFF_DIAG 16512                     // 16512+384 = 16896 <= 17408

__device__ float g_partials[NP];

__global__ __launch_bounds__(256, 2)
void sig_block_kernel(const float* __restrict__ X, const float* __restrict__ Y) {
    extern __shared__ float smem[];
    float* sA = smem;             // chunk of dx: 128 rows x CS   (GEMM phase)
    float* sB = smem + OFF_SB;    // chunk of dy: 128 rows x CS   (GEMM phase)
    float* sM = smem;             // 128x128 M matrix             (PDE phase, aliases sA/sB)

    const int bid = blockIdx.x;
    const int tid = threadIdx.x;

    // ---- decode (gram type, pair) ----
    int g, a, b;
    float w;
    if (bid < 2 * NPAIR_TRI) {
        g = (bid < NPAIR_TRI) ? 0 : 1;
        int t = bid - g * NPAIR_TRI;
        int aa = 0;
        while (t >= (AA - aa)) { t -= (AA - aa); ++aa; }
        a = aa; b = aa + t;
        w = (a == b) ? 1.0f : 2.0f;       // symmetric gram: off-diag counted twice
    } else {
        g = 2;
        int t = bid - 2 * NPAIR_TRI;
        a = t >> 6; b = t & 63;
        w = -2.0f;                        // -2 * mean(K_XY)
    }
    const float* srcA = (g == 1) ? (Y + (size_t)a * MSEQ * DD) : (X + (size_t)a * MSEQ * DD);
    const float* srcB = (g == 0) ? (X + (size_t)b * MSEQ * DD) : (Y + (size_t)b * MSEQ * DD);

    const int tx = tid & 15, ty = tid >> 4;

    float acc[64];
#pragma unroll
    for (int i = 0; i < 64; ++i) acc[i] = 0.0f;

    // ==== two K-chunks: load increments (coalesced, conflict-free), then FMA ====
    for (int kc = 0; kc < 2; ++kc) {
        const int k0 = kc * CH;
        if (kc) __syncthreads();   // protect previous chunk reads before overwrite

        // load chunk: 2048 float4 per tensor; idx = (i<<4)|c4, lanes sweep c4 -> coalesced
#pragma unroll
        for (int j = 0; j < 8; ++j) {
            int idx = tid + j * 256;
            int i  = idx >> 4;
            int c4 = (idx & 15) << 2;            // 0,4,...,60
            const float4* pa = reinterpret_cast<const float4*>(&srcA[i * DD + k0 + c4]);
            const float4* pb = reinterpret_cast<const float4*>(&srcB[i * DD + k0 + c4]);
            float4 ca = pa[0], cb = pb[0];
            float4 na, nb;
            if (i < MMI) { na = pa[DD / 4]; nb = pb[DD / 4]; }
            else         { na = ca;         nb = cb;         }  // row 127 -> inc 0
            float4 ia = make_float4(na.x - ca.x, na.y - ca.y, na.z - ca.z, na.w - ca.w);
            float4 ib = make_float4(nb.x - cb.x, nb.y - cb.y, nb.z - cb.z, nb.w - cb.w);
            *reinterpret_cast<float4*>(&sA[i * CS + c4]) = ia;
            *reinterpret_cast<float4*>(&sB[i * CS + c4]) = ib;
        }
        __syncthreads();

        // GEMM on this chunk: rows {8ty+m}, cols {tx+16k}
#pragma unroll 4
        for (int d4 = 0; d4 < CH; d4 += 4) {
            float4 af[8];
#pragma unroll
            for (int m = 0; m < 8; ++m)
                af[m] = *reinterpret_cast<const float4*>(&sA[(8 * ty + m) * CS + d4]);
#pragma unroll
            for (int k = 0; k < 8; ++k) {
                float4 bf = *reinterpret_cast<const float4*>(&sB[(tx + 16 * k) * CS + d4]);
#pragma unroll
                for (int m = 0; m < 8; ++m) {
                    float s = acc[m * 8 + k];
                    s = fmaf(af[m].x, bf.x, s);
                    s = fmaf(af[m].y, bf.y, s);
                    s = fmaf(af[m].z, bf.z, s);
                    s = fmaf(af[m].w, bf.w, s);
                    acc[m * 8 + k] = s;
                }
            }
        }
    }
    __syncthreads();   // all chunk reads done; safe to overwrite with sM

    // ---- write M (row stride 128): lanes sweep tx -> conflict-free ----
#pragma unroll
    for (int m = 0; m < 8; ++m)
#pragma unroll
        for (int k = 0; k < 8; ++k)
            sM[(8 * ty + m) * 128 + (tx + 16 * k)] = acc[m * 8 + k];
    __syncthreads();

    // ---- PDE: anti-diagonal wavefront over K (128x128, boundaries = 1) ----
    // K[p][q] = K[p][q-1] + K[p-1][q] + K[p-1][q-1]*(M[p-1][q-1]-1), p,q>=1
    // Diagonal reads of sM have lane stride 127 (odd) -> conflict-free.
    float* pp = smem + OFF_DIAG;        // diag d-2
    float* pv = smem + OFF_DIAG + 128;  // diag d-1
    float* cu = smem + OFF_DIAG + 256;  // diag d

    float result = 0.0f;
    for (int d = 0; d <= 254; ++d) {
        if (tid < 128) {
            int q = d - tid;
            if (q >= 0 && q < 128) {
                float v;
                if (tid == 0 || q == 0) {
                    v = 1.0f;
                } else {
                    v = pv[tid] + pv[tid - 1]
                      + pp[tid - 1] * (sM[(tid - 1) * 128 + (q - 1)] - 1.0f);
                }
                cu[tid] = v;
                result = v;   // thread 127 at d=254 holds K[127][127]
            }
        }
        __syncthreads();
        float* t = pp; pp = pv; pv = cu; cu = t;
    }

    if (tid == 127) g_partials[bid] = w * result;
}

__global__ void sig_reduce_kernel(float* __restrict__ out) {
    __shared__ double sh[256];
    const int tid = threadIdx.x;
    double acc = 0.0;
    for (int i = tid; i < NP; i += 256) acc += (double)g_partials[i];
    sh[tid] = acc;
    __syncthreads();
    for (int s = 128; s > 0; s >>= 1) {
        if (tid < s) sh[tid] += sh[tid + s];
        __syncthreads();
    }
    if (tid == 0) out[0] = (float)(sh[0] * (1.0 / 4096.0));
}

extern "C" void kernel_launch(void* const* d_in, const int* in_sizes, int n_in,
                              void* d_out, int out_size) {
    const float* X = (const float*)d_in[0];
    const float* Y = (const float*)d_in[1];
    float* out = (float*)d_out;

    cudaFuncSetAttribute(sig_block_kernel,
                         cudaFuncAttributeMaxDynamicSharedMemorySize, SMEM_BYTES);

    sig_block_kernel<<<NP, 256, SMEM_BYTES>>>(X, Y);
    sig_reduce_kernel<<<1, 256>>>(out);
}

// round 5
// speedup vs baseline: 5.1539x; 1.6058x over previous
#include <cuda_runtime.h>
#include <cuda_bf16.h>
#include <cstdint>

// ---------------- problem constants ----------------
#define AA 64
#define MSEQ 128
#define DD 128
#define MMI 127

#define NPAIR_TRI 2080
#define NP (2*NPAIR_TRI + AA*AA)          // 8256 pair-blocks

// ---------------- device scratch (no allocs) ----------------
// bf16 hi/lo increment tiles: [tsr(2)][seq(64)][row(128)][col(128)]
__device__ __align__(16) __nv_bfloat16 g_hi[2*64*128*128];   // 4 MB
__device__ __align__(16) __nv_bfloat16 g_lo[2*64*128*128];   // 4 MB
__device__ float g_partials[NP];

// ---------------- smem byte map (block kernel) ----------------
// GEMM phase: 4 chunk buffers, 128 rows x 144B (64 bf16 + 8 pad)
#define ROWB 144
#define SM_A_HI 0
#define SM_A_LO 18432
#define SM_B_HI 36864
#define SM_B_LO 55296
#define SMEM_BYTES 73728
// PDE phase (aliases buffers): sM fp32 128 x 130, then 3 diag buffers
#define SM_STRIDE 130
#define DIAG_OFF 16640                    // float index: 128*130 = 16640; +384 <= 18432 floats

__device__ __forceinline__ uint32_t smem_u32(const void* p) {
    uint32_t a;
    asm("{ .reg .u64 t; cvta.to.shared.u64 t, %1; cvt.u32.u64 %0, t; }" : "=r"(a) : "l"(p));
    return a;
}

__device__ __forceinline__ void ldsm4(uint32_t* r, uint32_t addr) {
    asm volatile("ldmatrix.sync.aligned.m8n8.x4.shared.b16 {%0,%1,%2,%3}, [%4];"
        : "=r"(r[0]), "=r"(r[1]), "=r"(r[2]), "=r"(r[3]) : "r"(addr));
}

__device__ __forceinline__ void mma16816(float* c, const uint32_t* a,
                                         uint32_t b0, uint32_t b1) {
    asm volatile(
        "mma.sync.aligned.m16n8k16.row.col.f32.bf16.bf16.f32 "
        "{%0,%1,%2,%3}, {%4,%5,%6,%7}, {%8,%9}, {%0,%1,%2,%3};"
        : "+f"(c[0]), "+f"(c[1]), "+f"(c[2]), "+f"(c[3])
        : "r"(a[0]), "r"(a[1]), "r"(a[2]), "r"(a[3]), "r"(b0), "r"(b1));
}

// ---------------- precompute: bf16 hi/lo increments ----------------
__global__ __launch_bounds__(256)
void sig_precompute_kernel(const float* __restrict__ X, const float* __restrict__ Y) {
    const int blk = blockIdx.x;                 // tsr*64 + seq
    const int seq = blk & 63;
    const int tsr = blk >> 6;
    const float* src = (tsr ? Y : X) + (size_t)seq * MSEQ * DD;
    __nv_bfloat16* hi = g_hi + (size_t)blk * 128 * 128;
    __nv_bfloat16* lo = g_lo + (size_t)blk * 128 * 128;

    const int tid = threadIdx.x;
#pragma unroll
    for (int i = 0; i < 16; ++i) {
        int idx = tid + i * 256;                // 0..4095 float4 groups
        int r  = idx >> 5;
        int c4 = (idx & 31) << 2;
        float4 cur = *reinterpret_cast<const float4*>(src + r * DD + c4);
        float4 nxt = (r < MMI) ? *reinterpret_cast<const float4*>(src + (r + 1) * DD + c4) : cur;
        float i0 = nxt.x - cur.x, i1 = nxt.y - cur.y, i2 = nxt.z - cur.z, i3 = nxt.w - cur.w;
        __nv_bfloat16 h0 = __float2bfloat16(i0), h1 = __float2bfloat16(i1);
        __nv_bfloat16 h2 = __float2bfloat16(i2), h3 = __float2bfloat16(i3);
        __nv_bfloat16 l0 = __float2bfloat16(i0 - __bfloat162float(h0));
        __nv_bfloat16 l1 = __float2bfloat16(i1 - __bfloat162float(h1));
        __nv_bfloat16 l2 = __float2bfloat16(i2 - __bfloat162float(h2));
        __nv_bfloat16 l3 = __float2bfloat16(i3 - __bfloat162float(h3));
        __nv_bfloat162 hp0(h0, h1), hp1(h2, h3), lp0(l0, l1), lp1(l2, l3);
        uint2 hv, lv;
        hv.x = *reinterpret_cast<uint32_t*>(&hp0); hv.y = *reinterpret_cast<uint32_t*>(&hp1);
        lv.x = *reinterpret_cast<uint32_t*>(&lp0); lv.y = *reinterpret_cast<uint32_t*>(&lp1);
        *reinterpret_cast<uint2*>(hi + r * 128 + c4) = hv;
        *reinterpret_cast<uint2*>(lo + r * 128 + c4) = lv;
    }
}

// ---------------- fused per-pair kernel ----------------
__global__ __launch_bounds__(256, 2)
void sig_block_kernel() {
    extern __shared__ unsigned char smem[];
    const uint32_t sbase = smem_u32(smem);
    const int bid = blockIdx.x;
    const int tid = threadIdx.x;
    const int wid = tid >> 5, lane = tid & 31;

    // ---- decode (gram type, pair) ----
    int g, a, b;
    float w;
    if (bid < 2 * NPAIR_TRI) {
        g = (bid < NPAIR_TRI) ? 0 : 1;
        int t = bid - g * NPAIR_TRI;
        int aa = 0;
        while (t >= (AA - aa)) { t -= (AA - aa); ++aa; }
        a = aa; b = aa + t;
        w = (a == b) ? 1.0f : 2.0f;
    } else {
        g = 2;
        int t = bid - 2 * NPAIR_TRI;
        a = t >> 6; b = t & 63;
        w = -2.0f;
    }
    const int idxA = ((g == 1) ? 64 : 0) + a;     // Y for YY else X
    const int idxB = ((g == 0) ? 0 : 64) + b;     // X for XX else Y
    const __nv_bfloat16* gAh = g_hi + (size_t)idxA * 16384;
    const __nv_bfloat16* gAl = g_lo + (size_t)idxA * 16384;
    const __nv_bfloat16* gBh = g_hi + (size_t)idxB * 16384;
    const __nv_bfloat16* gBl = g_lo + (size_t)idxB * 16384;

    // ---- per-thread ldmatrix address offsets ----
    // A x4 blocks: 0:(m0-7,k0) 1:(m8-15,k0) 2:(m0-7,k8) 3:(m8-15,k8)
    const int ablk = lane >> 3;
    const int arow = ((ablk & 1) << 3) + (lane & 7);
    const uint32_t aoff = (uint32_t)((16 * wid + arow) * ROWB + ((ablk >> 1) << 4));
    // B x4 blocks (two n8 tiles): 0:(t0,k0) 1:(t0,k8) 2:(t1,k0) 3:(t1,k8)
    const int bblk = lane >> 3;
    const uint32_t boff = (uint32_t)((((bblk >> 1) << 3) + (lane & 7)) * ROWB + ((bblk & 1) << 4));

    float acc[64];
#pragma unroll
    for (int i = 0; i < 64; ++i) acc[i] = 0.0f;

#pragma unroll
    for (int kc = 0; kc < 2; ++kc) {
        if (kc) __syncthreads();   // chunk0 fragment reads done before overwrite

        // ---- cooperative load of 4 chunk buffers (coalesced 128B rows) ----
#pragma unroll
        for (int i = 0; i < 4; ++i) {
            int idx = tid + i * 256;            // 0..1023 16B-chunks per buffer
            int r = idx >> 3, c = idx & 7;
            size_t go = (size_t)r * 128 + kc * 64 + c * 8;   // bf16 elems
            uint32_t so = (uint32_t)(r * ROWB + c * 16);
            *reinterpret_cast<uint4*>(smem + SM_A_HI + so) = *reinterpret_cast<const uint4*>(gAh + go);
            *reinterpret_cast<uint4*>(smem + SM_A_LO + so) = *reinterpret_cast<const uint4*>(gAl + go);
            *reinterpret_cast<uint4*>(smem + SM_B_HI + so) = *reinterpret_cast<const uint4*>(gBh + go);
            *reinterpret_cast<uint4*>(smem + SM_B_LO + so) = *reinterpret_cast<const uint4*>(gBl + go);
        }
        __syncthreads();

        // ---- warp GEMM: m16 (rows 16*wid..) x n128, k=64 in 4 k16 steps ----
#pragma unroll
        for (int kk = 0; kk < 4; ++kk) {
            uint32_t ah[4], al[4];
            ldsm4(ah, sbase + SM_A_HI + aoff + kk * 32);
            ldsm4(al, sbase + SM_A_LO + aoff + kk * 32);
#pragma unroll
            for (int j2 = 0; j2 < 8; ++j2) {
                uint32_t bh[4], bl[4];
                uint32_t bo = boff + j2 * (16 * ROWB) + kk * 32;
                ldsm4(bh, sbase + SM_B_HI + bo);
                ldsm4(bl, sbase + SM_B_LO + bo);
                float* c0 = acc + (2 * j2) * 4;
                float* c1 = acc + (2 * j2 + 1) * 4;
                mma16816(c0, ah, bh[0], bh[1]);   // hi*hi
                mma16816(c0, ah, bl[0], bl[1]);   // hi*lo
                mma16816(c0, al, bh[0], bh[1]);   // lo*hi
                mma16816(c1, ah, bh[2], bh[3]);
                mma16816(c1, ah, bl[2], bl[3]);
                mma16816(c1, al, bh[2], bh[3]);
            }
        }
    }
    __syncthreads();   // all fragment reads done; safe to overwrite with sM

    // ---- epilogue: acc -> sM (fp32, stride 130) ----
    float* sM = reinterpret_cast<float*>(smem);
    {
        const int r0 = 16 * wid + (lane >> 2);
        const int cb = (lane & 3) << 1;
#pragma unroll
        for (int j = 0; j < 16; ++j) {
            float* c = acc + j * 4;
            *reinterpret_cast<float2*>(&sM[r0 * SM_STRIDE + 8 * j + cb])       = make_float2(c[0], c[1]);
            *reinterpret_cast<float2*>(&sM[(r0 + 8) * SM_STRIDE + 8 * j + cb]) = make_float2(c[2], c[3]);
        }
    }
    __syncthreads();

    // ---- PDE: anti-diagonal wavefront, K 128x128, boundaries = 1 ----
    // K[p][q] = K[p][q-1] + K[p-1][q] + K[p-1][q-1]*(M[p-1][q-1]-1)
    // sM diagonal reads: lane stride SM_STRIDE-1 = 129 (odd) -> conflict-free
    float* pp = reinterpret_cast<float*>(smem) + DIAG_OFF;
    float* pv = pp + 128;
    float* cu = pp + 256;

    float result = 0.0f;
    for (int d = 0; d <= 254; ++d) {
        if (tid < 128) {
            int q = d - tid;
            if (q >= 0 && q < 128) {
                float v;
                if (tid == 0 || q == 0) {
                    v = 1.0f;
                } else {
                    v = pv[tid] + pv[tid - 1]
                      + pp[tid - 1] * (sM[(tid - 1) * SM_STRIDE + (q - 1)] - 1.0f);
                }
                cu[tid] = v;
                result = v;                     // thread 127 at d=254 holds K[127][127]
            }
        }
        __syncthreads();
        float* t = pp; pp = pv; pv = cu; cu = t;
    }

    if (tid == 127) g_partials[bid] = w * result;
}

// ---------------- deterministic FP64 reduction ----------------
__global__ void sig_reduce_kernel(float* __restrict__ out) {
    __shared__ double sh[256];
    const int tid = threadIdx.x;
    double acc = 0.0;
    for (int i = tid; i < NP; i += 256) acc += (double)g_partials[i];
    sh[tid] = acc;
    __syncthreads();
    for (int s = 128; s > 0; s >>= 1) {
        if (tid < s) sh[tid] += sh[tid + s];
        __syncthreads();
    }
    if (tid == 0) out[0] = (float)(sh[0] * (1.0 / 4096.0));
}

extern "C" void kernel_launch(void* const* d_in, const int* in_sizes, int n_in,
                              void* d_out, int out_size) {
    const float* X = (const float*)d_in[0];
    const float* Y = (const float*)d_in[1];
    float* out = (float*)d_out;

    cudaFuncSetAttribute(sig_block_kernel,
                         cudaFuncAttributeMaxDynamicSharedMemorySize, SMEM_BYTES);

    sig_precompute_kernel<<<128, 256>>>(X, Y);
    sig_block_kernel<<<NP, 256, SMEM_BYTES>>>();
    sig_reduce_kernel<<<1, 256>>>(out);
}